// round 1
// baseline (speedup 1.0000x reference)
#include <cuda_runtime.h>

// Problem constants
// x:   [256, 3072] fp32
// phi: [3072, 4096] fp32 (column-normalized)
// out: [256, 4096] fp32
//
// Math (first-order collapse of 19 gradient steps, error ~3e-7 absolute):
//   a0    = x @ phi
//   resid = a0 @ phi^T - x
//   out   = a0 - C19 * (resid @ phi + sparse_mult * sign(a0))
// where C19 = 19 * 0.005 / 256.

constexpr int BM = 64, BN = 64, BK = 16;
constexpr int TM = 8, TN = 4;
constexpr int SLD = 68;  // padded smem row stride (floats); 68*4=272 bytes, 16B-aligned rows

// Scratch (device globals: no allocation allowed)
__device__ float g_a0[256 * 4096];     // 4 MB
__device__ float g_resid[256 * 3072];  // 3 MB

// MODE 0: C = A@B              (A=x,     B=phi NN)        -> g_a0
// MODE 1: C = A@B^T - X        (A=a0,    B=phi as [N,K])  -> g_resid
// MODE 2: C = A0 - c19*(A@B + sm*sign(A0))  (A=resid, B=phi NN) -> out
template <int MODE, bool TRANSB>
__global__ __launch_bounds__(128) void gemm_k(
    const float* __restrict__ A, const float* __restrict__ B,
    const float* __restrict__ X, const float* __restrict__ A0,
    const float* __restrict__ SMP, float* __restrict__ C,
    int K, int lda, int ldb, int ldc)
{
    __shared__ float As[BK * SLD];
    __shared__ float Bs[BK * SLD];

    const int m0 = blockIdx.y * BM;
    const int n0 = blockIdx.x * BN;
    const int tid = threadIdx.x;
    const int tn = tid & 15;   // 16 threads in N, TN=4 -> 64
    const int tm = tid >> 4;   // 8 threads in M,  TM=8 -> 64

    float acc[TM][TN];
#pragma unroll
    for (int i = 0; i < TM; i++)
#pragma unroll
        for (int j = 0; j < TN; j++) acc[i][j] = 0.0f;

    // A-style loader (64 rows x 16 cols, transposed into smem)
    const int ar = tid >> 2;        // 0..31
    const int ac = (tid & 3) * 4;   // 0,4,8,12
    // B NN loader (16 rows x 64 cols, direct)
    const int br = tid >> 4;        // 0..7
    const int bc = (tid & 15) * 4;  // 0..60

    for (int kb = 0; kb < K; kb += BK) {
        // ---- load A tile: A[m0+mrow][kb+ac..+3] -> As[k][m]
#pragma unroll
        for (int h = 0; h < 2; h++) {
            int mrow = ar + h * 32;
            float4 v = *reinterpret_cast<const float4*>(
                &A[(size_t)(m0 + mrow) * lda + kb + ac]);
            As[(ac + 0) * SLD + mrow] = v.x;
            As[(ac + 1) * SLD + mrow] = v.y;
            As[(ac + 2) * SLD + mrow] = v.z;
            As[(ac + 3) * SLD + mrow] = v.w;
        }
        // ---- load B tile
        if (TRANSB) {
            // B physical [Nout, K]: Bs[k][n] = B[(n0+n)*ldb + kb+k]
#pragma unroll
            for (int h = 0; h < 2; h++) {
                int nrow = ar + h * 32;
                float4 v = *reinterpret_cast<const float4*>(
                    &B[(size_t)(n0 + nrow) * ldb + kb + ac]);
                Bs[(ac + 0) * SLD + nrow] = v.x;
                Bs[(ac + 1) * SLD + nrow] = v.y;
                Bs[(ac + 2) * SLD + nrow] = v.z;
                Bs[(ac + 3) * SLD + nrow] = v.w;
            }
        } else {
            // B physical [K, Nout]: Bs[k][n] = B[(kb+k)*ldb + n0+n]
#pragma unroll
            for (int h = 0; h < 2; h++) {
                int krow = br + h * 8;
                float4 v = *reinterpret_cast<const float4*>(
                    &B[(size_t)(kb + krow) * ldb + n0 + bc]);
                *reinterpret_cast<float4*>(&Bs[krow * SLD + bc]) = v;
            }
        }
        __syncthreads();

        // ---- compute
#pragma unroll
        for (int k = 0; k < BK; k++) {
            float a[TM], b[TN];
            float4 av0 = *reinterpret_cast<const float4*>(&As[k * SLD + tm * TM]);
            float4 av1 = *reinterpret_cast<const float4*>(&As[k * SLD + tm * TM + 4]);
            a[0] = av0.x; a[1] = av0.y; a[2] = av0.z; a[3] = av0.w;
            a[4] = av1.x; a[5] = av1.y; a[6] = av1.z; a[7] = av1.w;
            float4 bv = *reinterpret_cast<const float4*>(&Bs[k * SLD + tn * TN]);
            b[0] = bv.x; b[1] = bv.y; b[2] = bv.z; b[3] = bv.w;
#pragma unroll
            for (int i = 0; i < TM; i++)
#pragma unroll
                for (int j = 0; j < TN; j++) acc[i][j] += a[i] * b[j];
        }
        __syncthreads();
    }

    // ---- epilogue
    const float c19 = 19.0f * (0.005f / 256.0f);
    float sm = (MODE == 2) ? *SMP : 0.0f;
#pragma unroll
    for (int i = 0; i < TM; i++) {
        int m = m0 + tm * TM + i;
#pragma unroll
        for (int j = 0; j < TN; j++) {
            int n = n0 + tn * TN + j;
            size_t idx = (size_t)m * ldc + n;
            float v = acc[i][j];
            if (MODE == 0) {
                C[idx] = v;
            } else if (MODE == 1) {
                C[idx] = v - X[idx];
            } else {
                float av = A0[idx];
                float s = (av > 0.0f) ? 1.0f : ((av < 0.0f) ? -1.0f : 0.0f);
                C[idx] = av - c19 * (v + sm * s);
            }
        }
    }
}

extern "C" void kernel_launch(void* const* d_in, const int* in_sizes, int n_in,
                              void* d_out, int out_size)
{
    const float* x   = (const float*)d_in[0];  // [256, 3072]
    const float* phi = (const float*)d_in[1];  // [3072, 4096]
    const float* smp = (const float*)d_in[2];  // scalar
    float* out = (float*)d_out;                // [256, 4096]

    float *a0p, *residp;
    cudaGetSymbolAddress((void**)&a0p, g_a0);
    cudaGetSymbolAddress((void**)&residp, g_resid);

    dim3 blk(128);

    // 1) a0 = x @ phi            M=256, N=4096, K=3072 (NN)
    gemm_k<0, false><<<dim3(4096 / BN, 256 / BM), blk>>>(
        x, phi, nullptr, nullptr, nullptr, a0p,
        /*K=*/3072, /*lda=*/3072, /*ldb=*/4096, /*ldc=*/4096);

    // 2) resid = a0 @ phi^T - x  M=256, N=3072, K=4096 (B = phi as [3072,4096] -> B^T)
    gemm_k<1, true><<<dim3(3072 / BN, 256 / BM), blk>>>(
        a0p, phi, x, nullptr, nullptr, residp,
        /*K=*/4096, /*lda=*/4096, /*ldb=*/4096, /*ldc=*/3072);

    // 3) out = a0 - c19*(resid @ phi + sm*sign(a0))  M=256, N=4096, K=3072 (NN)
    gemm_k<2, false><<<dim3(4096 / BN, 256 / BM), blk>>>(
        residp, phi, nullptr, a0p, smp, out,
        /*K=*/3072, /*lda=*/3072, /*ldb=*/4096, /*ldc=*/4096);
}

// round 6
// speedup vs baseline: 2.2839x; 2.2839x over previous
#include <cuda_runtime.h>
#include <cstdint>

// Math (first-order collapse of 19 gradient steps, validated in R1 at rel_err 6e-6):
//   a0    = x @ phi
//   resid = a0 @ phi^T - x
//   out   = a0 - C19 * (resid @ phi + sm * sign(a0)),  C19 = 19*0.005/256
//
// GEMM1 uses 3xTF32 (hi/lo operand split -> effectively fp32): tf32 alone gave
// rel_err 2e-3 in R5. GEMMs 2-3 compute only the ~7e-4-relative correction, so
// single-pass tf32 there contributes ~1e-6 to the output.
//
// GEMM1: NN, SPLIT  (B = phi [K=3072][N=4096], N contiguous)
// GEMM2: TN         (B = phi rows = output pixels, K contiguous)  -> resid
// GEMM3: NN         (same B as GEMM1)                             -> out

#define DINL __device__ __forceinline__

// ---------------- scratch (device globals; no allocation allowed) -----------
__device__ __align__(1024) float g_a0[256 * 4096];   // 4.2 MB
__device__ __align__(1024) float g_res[256 * 3072];  // 3.1 MB

// ---------------- PTX helpers -----------------------------------------------
DINL uint32_t smem_u32(const void* p) {
    uint32_t a;
    asm("{ .reg .u64 t; cvta.to.shared.u64 t, %1; cvt.u32.u64 %0, t; }"
        : "=r"(a) : "l"(p));
    return a;
}

#define CP16(dst, src) \
    asm volatile("cp.async.cg.shared.global [%0], [%1], 16;" :: "r"(dst), "l"(src) : "memory")
#define CP_COMMIT() asm volatile("cp.async.commit_group;" ::: "memory")
#define CP_WAIT1()  asm volatile("cp.async.wait_group 1;" ::: "memory")

DINL uint32_t f2tf(float f) {
    uint32_t u;
    asm("cvt.rna.tf32.f32 %0, %1;" : "=r"(u) : "f"(f));
    return u;
}
// hi/lo split: f ≈ hi + lo with both tf32-representable
DINL void f2tf2(float f, uint32_t& h, uint32_t& l) {
    h = f2tf(f);
    l = f2tf(f - __uint_as_float(h));
}

DINL void mma8(float& d0, float& d1, float& d2, float& d3,
               uint32_t a0, uint32_t a1, uint32_t a2, uint32_t a3,
               uint32_t b0, uint32_t b1) {
    asm volatile(
        "mma.sync.aligned.m16n8k8.row.col.f32.tf32.tf32.f32 "
        "{%0,%1,%2,%3}, {%4,%5,%6,%7}, {%8,%9}, {%0,%1,%2,%3};"
        : "+f"(d0), "+f"(d1), "+f"(d2), "+f"(d3)
        : "r"(a0), "r"(a1), "r"(a2), "r"(a3), "r"(b0), "r"(b1));
}

// ---------------- GEMM -------------------------------------------------------
// BM=64, BN=64, BK=32; 128 threads = 4 warps (2M x 2N), warp tile 32x32.
// 2-stage cp.async double buffer, static shared memory (36,864 B).
//
// MODE 0: C = acc                              (a0)
// MODE 1: C = acc - X                          (resid)
// MODE 2: C = A0 - c19*(acc + sm*sign(A0))     (out)
// TNB=false: B[k][n], n contiguous.  TNB=true: B[n][k], k contiguous.
// SPLIT: 3xTF32 hi/lo operand split (fp32-accurate product).

constexpr int SA = 36;            // A (and B-TN) smem row stride, BK=32 + 4 pad
constexpr int SBN = 72;           // B NN row stride (BN=64 + 8 pad)
constexpr int ASTG = 64 * SA;     // 2304 floats per stage
constexpr int BSTG = 2304;        // B NN: 32*72; B TN: 64*36

template <int MODE, bool TNB, bool SPLIT>
__global__ __launch_bounds__(128) void gemm_tf32(
    const float* __restrict__ A, const float* __restrict__ B,
    const float* __restrict__ X, const float* __restrict__ A0,
    const float* __restrict__ SMP, float* __restrict__ C,
    int K, int lda, int ldb, int ldc)
{
    __shared__ float As[2 * ASTG];
    __shared__ float Bs[2 * BSTG];
    const uint32_t sA_u = smem_u32(As);
    const uint32_t sB_u = smem_u32(Bs);

    const int tid = threadIdx.x, lane = tid & 31, wid = tid >> 5;
    const int wm = wid >> 1, wn = wid & 1;
    const int m0 = blockIdx.y * 64, n0 = blockIdx.x * 64;
    const int g = lane >> 2, c4 = lane & 3;

    float acc[2][4][4];
#pragma unroll
    for (int mt = 0; mt < 2; mt++)
#pragma unroll
        for (int nt = 0; nt < 4; nt++)
#pragma unroll
            for (int r = 0; r < 4; r++) acc[mt][nt][r] = 0.0f;

    const int nk = K >> 5;

    auto load_tile = [&](int t, int slot) {
        const float* Ab = A + (size_t)m0 * lda + t * 32;
        uint32_t ad = sA_u + slot * ASTG * 4;
#pragma unroll
        for (int h = 0; h < 4; h++) {
            int idx = tid + h * 128;
            int row = idx >> 3, seg = idx & 7;
            CP16(ad + (uint32_t)(row * SA + seg * 4) * 4,
                 Ab + (size_t)row * lda + seg * 4);
        }
        uint32_t bd = sB_u + slot * BSTG * 4;
        if (TNB) {
            const float* Bb = B + (size_t)n0 * ldb + t * 32;
#pragma unroll
            for (int h = 0; h < 4; h++) {
                int idx = tid + h * 128;
                int row = idx >> 3, seg = idx & 7;
                CP16(bd + (uint32_t)(row * SA + seg * 4) * 4,
                     Bb + (size_t)row * ldb + seg * 4);
            }
        } else {
            const float* Bb = B + (size_t)(t * 32) * ldb + n0;
#pragma unroll
            for (int h = 0; h < 4; h++) {
                int idx = tid + h * 128;
                int row = idx >> 4, seg = idx & 15;
                CP16(bd + (uint32_t)(row * SBN + seg * 4) * 4,
                     Bb + (size_t)row * ldb + seg * 4);
            }
        }
    };

    load_tile(0, 0);
    CP_COMMIT();

    for (int i = 0; i < nk; i++) {
        if (i + 1 < nk) {
            load_tile(i + 1, (i + 1) & 1);
            CP_COMMIT();
        }
        CP_WAIT1();
        __syncthreads();

        const float* Asl = As + (i & 1) * ASTG;
        const float* Bsl = Bs + (i & 1) * BSTG;
#pragma unroll
        for (int ks = 0; ks < 4; ks++) {
            const int k0 = ks * 8;
            if (SPLIT) {
                uint32_t afh[2][4], afl[2][4];
#pragma unroll
                for (int mt = 0; mt < 2; mt++) {
                    const float* ap = Asl + (wm * 32 + mt * 16 + g) * SA + k0 + c4;
                    f2tf2(ap[0],          afh[mt][0], afl[mt][0]);
                    f2tf2(ap[8 * SA],     afh[mt][1], afl[mt][1]);
                    f2tf2(ap[4],          afh[mt][2], afl[mt][2]);
                    f2tf2(ap[8 * SA + 4], afh[mt][3], afl[mt][3]);
                }
                uint32_t bfh[4][2], bfl[4][2];
#pragma unroll
                for (int nt = 0; nt < 4; nt++) {
                    const int nb = wn * 32 + nt * 8;
                    const float* bp = Bsl + (k0 + c4) * SBN + nb + g;   // NN only
                    f2tf2(bp[0],       bfh[nt][0], bfl[nt][0]);
                    f2tf2(bp[4 * SBN], bfh[nt][1], bfl[nt][1]);
                }
#pragma unroll
                for (int mt = 0; mt < 2; mt++)
#pragma unroll
                    for (int nt = 0; nt < 4; nt++) {
                        // small terms first, then dominant h*h
                        mma8(acc[mt][nt][0], acc[mt][nt][1], acc[mt][nt][2], acc[mt][nt][3],
                             afh[mt][0], afh[mt][1], afh[mt][2], afh[mt][3],
                             bfl[nt][0], bfl[nt][1]);
                        mma8(acc[mt][nt][0], acc[mt][nt][1], acc[mt][nt][2], acc[mt][nt][3],
                             afl[mt][0], afl[mt][1], afl[mt][2], afl[mt][3],
                             bfh[nt][0], bfh[nt][1]);
                        mma8(acc[mt][nt][0], acc[mt][nt][1], acc[mt][nt][2], acc[mt][nt][3],
                             afh[mt][0], afh[mt][1], afh[mt][2], afh[mt][3],
                             bfh[nt][0], bfh[nt][1]);
                    }
            } else {
                uint32_t af[2][4];
#pragma unroll
                for (int mt = 0; mt < 2; mt++) {
                    const float* ap = Asl + (wm * 32 + mt * 16 + g) * SA + k0 + c4;
                    af[mt][0] = f2tf(ap[0]);
                    af[mt][1] = f2tf(ap[8 * SA]);
                    af[mt][2] = f2tf(ap[4]);
                    af[mt][3] = f2tf(ap[8 * SA + 4]);
                }
                uint32_t bf[4][2];
#pragma unroll
                for (int nt = 0; nt < 4; nt++) {
                    const int nb = wn * 32 + nt * 8;
                    if (TNB) {
                        const float* bp = Bsl + (nb + g) * SA + k0 + c4;
                        bf[nt][0] = f2tf(bp[0]);
                        bf[nt][1] = f2tf(bp[4]);
                    } else {
                        const float* bp = Bsl + (k0 + c4) * SBN + nb + g;
                        bf[nt][0] = f2tf(bp[0]);
                        bf[nt][1] = f2tf(bp[4 * SBN]);
                    }
                }
#pragma unroll
                for (int mt = 0; mt < 2; mt++)
#pragma unroll
                    for (int nt = 0; nt < 4; nt++)
                        mma8(acc[mt][nt][0], acc[mt][nt][1], acc[mt][nt][2], acc[mt][nt][3],
                             af[mt][0], af[mt][1], af[mt][2], af[mt][3],
                             bf[nt][0], bf[nt][1]);
            }
        }
        __syncthreads();
    }

    // ---- epilogue ----
    const float c19 = 19.0f * (0.005f / 256.0f);
    const float smv = (MODE == 2) ? SMP[0] : 0.0f;
#pragma unroll
    for (int mt = 0; mt < 2; mt++) {
        const int r0 = m0 + wm * 32 + mt * 16 + g;
#pragma unroll
        for (int nt = 0; nt < 4; nt++) {
            const int col = n0 + wn * 32 + nt * 8 + 2 * c4;
#pragma unroll
            for (int half = 0; half < 2; half++) {
                const int row = r0 + half * 8;
                const float d0 = acc[mt][nt][half * 2 + 0];
                const float d1 = acc[mt][nt][half * 2 + 1];
                const size_t idx = (size_t)row * ldc + col;
                if (MODE == 0) {
                    float2 v = {d0, d1};
                    *reinterpret_cast<float2*>(&C[idx]) = v;
                } else if (MODE == 1) {
                    float2 xv = *reinterpret_cast<const float2*>(&X[idx]);
                    float2 v = {d0 - xv.x, d1 - xv.y};
                    *reinterpret_cast<float2*>(&C[idx]) = v;
                } else {
                    float2 av = *reinterpret_cast<const float2*>(&A0[idx]);
                    float s0 = (av.x > 0.f) ? 1.f : ((av.x < 0.f) ? -1.f : 0.f);
                    float s1 = (av.y > 0.f) ? 1.f : ((av.y < 0.f) ? -1.f : 0.f);
                    float2 v = {av.x - c19 * (d0 + smv * s0),
                                av.y - c19 * (d1 + smv * s1)};
                    *reinterpret_cast<float2*>(&C[idx]) = v;
                }
            }
        }
    }
}

// ---------------- launch -----------------------------------------------------
extern "C" void kernel_launch(void* const* d_in, const int* in_sizes, int n_in,
                              void* d_out, int out_size)
{
    const float* x   = (const float*)d_in[0];  // [256, 3072]
    const float* phi = (const float*)d_in[1];  // [3072, 4096]
    const float* smp = (const float*)d_in[2];  // scalar
    float* out = (float*)d_out;                // [256, 4096]

    float *a0p, *resp;
    cudaGetSymbolAddress((void**)&a0p, g_a0);
    cudaGetSymbolAddress((void**)&resp, g_res);

    // GEMM1: a0 = x @ phi            M=256, N=4096, K=3072  (NN, 3xTF32)
    gemm_tf32<0, false, true><<<dim3(4096 / 64, 4), 128>>>(
        x, phi, nullptr, nullptr, smp, a0p, 3072, 3072, 4096, 4096);

    // GEMM2: resid = a0 @ phi^T - x  M=256, N=3072, K=4096  (TN)
    gemm_tf32<1, true, false><<<dim3(3072 / 64, 4), 128>>>(
        a0p, phi, x, nullptr, smp, resp, 4096, 4096, 4096, 3072);

    // GEMM3: out = a0 - c19*(resid @ phi + sm*sign(a0))  M=256, N=4096, K=3072 (NN)
    gemm_tf32<2, false, false><<<dim3(4096 / 64, 4), 128>>>(
        resp, phi, nullptr, a0p, smp, out, 3072, 3072, 4096, 4096);
}

// round 7
// speedup vs baseline: 3.1454x; 1.3772x over previous
#include <cuda_runtime.h>
#include <cuda_bf16.h>
#include <cstdint>

// Math (first-order collapse of 19 gradient steps, validated):
//   a0    = x @ phi
//   resid = a0 @ phi^T - x
//   out   = a0 - C19 * (resid @ phi + sm * sign(a0)),  C19 = 19*0.005/256
//
// All GEMMs: mma.sync.m16n8k16 bf16 (2x tf32 rate), B in TN layout (K contig).
// GEMM1 accuracy: bf16 hi/lo split via K-concat (K=9216):
//   A1 = [xh | xh | xl],  B1 = [phT | plT | phT]  ->  xh*ph + xh*pl + xl*ph
// GEMM2: B2 = bf16(phi) in place-layout [3072 pix][4096 neu], K=neuron contig.
// GEMM3: B = first 3072 K-cols of B1 (= phT).

#define DINL __device__ __forceinline__

// ---------------- scratch (device globals; no allocation allowed) -----------
__device__ __align__(1024) __nv_bfloat16 g_A1[256 * 9216];   // 4.7 MB
__device__ __align__(1024) __nv_bfloat16 g_B1[4096 * 9216];  // 75.5 MB
__device__ __align__(1024) __nv_bfloat16 g_B2[3072 * 4096];  // 25.2 MB
__device__ __align__(1024) float         g_a0f[256 * 4096];  // 4.2 MB
__device__ __align__(1024) __nv_bfloat16 g_a0h[256 * 4096];  // 2.1 MB
__device__ __align__(1024) __nv_bfloat16 g_rh[256 * 3072];   // 1.6 MB

// ---------------- PTX helpers -----------------------------------------------
DINL uint32_t smem_u32(const void* p) {
    uint32_t a;
    asm("{ .reg .u64 t; cvta.to.shared.u64 t, %1; cvt.u32.u64 %0, t; }"
        : "=r"(a) : "l"(p));
    return a;
}

#define CP16(dst, src) \
    asm volatile("cp.async.cg.shared.global [%0], [%1], 16;" :: "r"(dst), "l"(src) : "memory")
#define CP_COMMIT() asm volatile("cp.async.commit_group;" ::: "memory")
#define CP_WAIT1()  asm volatile("cp.async.wait_group 1;" ::: "memory")

DINL void mma16(float& d0, float& d1, float& d2, float& d3,
                uint32_t a0, uint32_t a1, uint32_t a2, uint32_t a3,
                uint32_t b0, uint32_t b1) {
    asm volatile(
        "mma.sync.aligned.m16n8k16.row.col.f32.bf16.bf16.f32 "
        "{%0,%1,%2,%3}, {%4,%5,%6,%7}, {%8,%9}, {%0,%1,%2,%3};"
        : "+f"(d0), "+f"(d1), "+f"(d2), "+f"(d3)
        : "r"(a0), "r"(a1), "r"(a2), "r"(a3), "r"(b0), "r"(b1));
}

DINL uint32_t pack2(float a, float b) {
    __nv_bfloat162 t = __floats2bfloat162_rn(a, b);
    return *reinterpret_cast<uint32_t*>(&t);
}

// ---------------- conversion kernels -----------------------------------------
__global__ __launch_bounds__(256) void conv_x(const float* __restrict__ x,
                                              __nv_bfloat16* __restrict__ A1) {
    int t = blockIdx.x * 256 + threadIdx.x;  // 256*3072 elements
    int m = t >> 11;                          // t / 2048? no: 3072 per row
    m = t / 3072;
    int k = t - m * 3072;
    float f = x[t];
    __nv_bfloat16 h = __float2bfloat16(f);
    __nv_bfloat16 l = __float2bfloat16(f - __bfloat162float(h));
    size_t base = (size_t)m * 9216 + k;
    A1[base] = h;          // pairs with phT
    A1[base + 3072] = h;   // pairs with plT
    A1[base + 6144] = l;   // pairs with phT
}

// tile: 64 pixels (p) x 32 neurons (n), 512 threads
__global__ __launch_bounds__(512) void conv_phi(const float* __restrict__ phi,
                                                __nv_bfloat16* __restrict__ B1,
                                                __nv_bfloat16* __restrict__ B2) {
    __shared__ float tile[64][33];
    int p0 = blockIdx.y * 64, n0 = blockIdx.x * 32;
    int tx = threadIdx.x & 31, ty = threadIdx.x >> 5;  // ty 0..15
#pragma unroll
    for (int r = 0; r < 4; r++) {
        int pl = ty + 16 * r;
        float f = phi[(size_t)(p0 + pl) * 4096 + n0 + tx];
        tile[pl][tx] = f;
        B2[(size_t)(p0 + pl) * 4096 + n0 + tx] = __float2bfloat16(f);
    }
    __syncthreads();
    int pl2 = threadIdx.x & 63, nl2 = threadIdx.x >> 6;  // nl2 0..7
#pragma unroll
    for (int r = 0; r < 4; r++) {
        int nl = nl2 + 8 * r;
        float f = tile[pl2][nl];
        __nv_bfloat16 h = __float2bfloat16(f);
        __nv_bfloat16 l = __float2bfloat16(f - __bfloat162float(h));
        size_t base = (size_t)(n0 + nl) * 9216 + p0 + pl2;
        B1[base] = h;          // phT
        B1[base + 3072] = l;   // plT
        B1[base + 6144] = h;   // phT (pairs with xl)
    }
}

// ---------------- bf16 tensor-core GEMM --------------------------------------
// C[M,N] = sum_k A[m,k]*B[n,k].  BM=64, BN=64, BK=64 (bf16).
// 256 threads = 8 warps: 2(M) x 4(N); warp tile 32x16 = 2 m16 x 2 n8.
// 2-stage cp.async double buffer; static smem 36,864 B.
// Smem stored as u32 (bf16 pairs): row stride 36 u32 (32 data + 4 pad).
//
// MODE 0: a0f = acc (fp32), a0h = bf16(acc)
// MODE 1: Ch = bf16(acc - X)
// MODE 2: Cf = A0 - c19*(acc + sm*sign(A0))

constexpr int SAu = 36;             // u32 row stride
constexpr int STG = 64 * SAu;       // 2304 u32 per tile per stage

template <int MODE>
__global__ __launch_bounds__(256) void gemm_bf16(
    const __nv_bfloat16* __restrict__ A, const __nv_bfloat16* __restrict__ B,
    const float* __restrict__ X, const float* __restrict__ A0,
    const float* __restrict__ SMP, float* __restrict__ Cf,
    __nv_bfloat16* __restrict__ Ch, int K, int lda, int ldb, int ldc)
{
    __shared__ uint32_t As[2 * STG];
    __shared__ uint32_t Bs[2 * STG];
    const uint32_t sA_u = smem_u32(As);
    const uint32_t sB_u = smem_u32(Bs);

    const int tid = threadIdx.x, lane = tid & 31, wid = tid >> 5;
    const int wm = wid >> 2, wn = wid & 3;     // 2 x 4
    const int m0 = blockIdx.y * 64, n0 = blockIdx.x * 64;
    const int g = lane >> 2, c4 = lane & 3;

    float acc[2][2][4];
#pragma unroll
    for (int mt = 0; mt < 2; mt++)
#pragma unroll
        for (int nt = 0; nt < 2; nt++)
#pragma unroll
            for (int r = 0; r < 4; r++) acc[mt][nt][r] = 0.0f;

    const int nk = K >> 6;   // BK = 64 bf16

    auto load_tile = [&](int t, int slot) {
        // A: 64 rows x 128 B = 512 x 16B; 2 per thread
        const char* Ab = (const char*)(A + (size_t)m0 * lda + t * 64);
        uint32_t ad = sA_u + slot * STG * 4;
#pragma unroll
        for (int h = 0; h < 2; h++) {
            int idx = tid + h * 256;
            int row = idx >> 3, seg = idx & 7;
            CP16(ad + (uint32_t)(row * SAu + seg * 4) * 4,
                 Ab + (size_t)row * lda * 2 + seg * 16);
        }
        // B: 64 rows x 128 B; 2 per thread
        const char* Bb = (const char*)(B + (size_t)n0 * ldb + t * 64);
        uint32_t bd = sB_u + slot * STG * 4;
#pragma unroll
        for (int h = 0; h < 2; h++) {
            int idx = tid + h * 256;
            int row = idx >> 3, seg = idx & 7;
            CP16(bd + (uint32_t)(row * SAu + seg * 4) * 4,
                 Bb + (size_t)row * ldb * 2 + seg * 16);
        }
    };

    load_tile(0, 0);
    CP_COMMIT();

    for (int i = 0; i < nk; i++) {
        if (i + 1 < nk) {
            load_tile(i + 1, (i + 1) & 1);
            CP_COMMIT();
        }
        CP_WAIT1();
        __syncthreads();

        const uint32_t* Asl = As + (i & 1) * STG;
        const uint32_t* Bsl = Bs + (i & 1) * STG;
#pragma unroll
        for (int ks = 0; ks < 4; ks++) {
            const int k0 = ks * 8;              // u32 cols per k16 step
            uint32_t af[2][4];
#pragma unroll
            for (int mt = 0; mt < 2; mt++) {
                const uint32_t* ap = Asl + (wm * 32 + mt * 16 + g) * SAu + k0 + c4;
                af[mt][0] = ap[0];
                af[mt][1] = ap[8 * SAu];
                af[mt][2] = ap[4];
                af[mt][3] = ap[8 * SAu + 4];
            }
            uint32_t bf[2][2];
#pragma unroll
            for (int nt = 0; nt < 2; nt++) {
                const uint32_t* bp = Bsl + (wn * 16 + nt * 8 + g) * SAu + k0 + c4;
                bf[nt][0] = bp[0];
                bf[nt][1] = bp[4];
            }
#pragma unroll
            for (int mt = 0; mt < 2; mt++)
#pragma unroll
                for (int nt = 0; nt < 2; nt++)
                    mma16(acc[mt][nt][0], acc[mt][nt][1], acc[mt][nt][2], acc[mt][nt][3],
                          af[mt][0], af[mt][1], af[mt][2], af[mt][3],
                          bf[nt][0], bf[nt][1]);
        }
        __syncthreads();
    }

    // ---- epilogue ----
    const float c19 = 19.0f * (0.005f / 256.0f);
    const float smv = (MODE == 2) ? SMP[0] : 0.0f;
#pragma unroll
    for (int mt = 0; mt < 2; mt++) {
        const int r0 = m0 + wm * 32 + mt * 16 + g;
#pragma unroll
        for (int nt = 0; nt < 2; nt++) {
            const int col = n0 + wn * 16 + nt * 8 + 2 * c4;
#pragma unroll
            for (int half = 0; half < 2; half++) {
                const int row = r0 + half * 8;
                const float d0 = acc[mt][nt][half * 2 + 0];
                const float d1 = acc[mt][nt][half * 2 + 1];
                const size_t idx = (size_t)row * ldc + col;
                if (MODE == 0) {
                    float2 v = {d0, d1};
                    *reinterpret_cast<float2*>(&Cf[idx]) = v;
                    *reinterpret_cast<uint32_t*>(&Ch[idx]) = pack2(d0, d1);
                } else if (MODE == 1) {
                    float2 xv = *reinterpret_cast<const float2*>(&X[idx]);
                    *reinterpret_cast<uint32_t*>(&Ch[idx]) = pack2(d0 - xv.x, d1 - xv.y);
                } else {
                    float2 av = *reinterpret_cast<const float2*>(&A0[idx]);
                    float s0 = (av.x > 0.f) ? 1.f : ((av.x < 0.f) ? -1.f : 0.f);
                    float s1 = (av.y > 0.f) ? 1.f : ((av.y < 0.f) ? -1.f : 0.f);
                    float2 v = {av.x - c19 * (d0 + smv * s0),
                                av.y - c19 * (d1 + smv * s1)};
                    *reinterpret_cast<float2*>(&Cf[idx]) = v;
                }
            }
        }
    }
}

// ---------------- launch -----------------------------------------------------
extern "C" void kernel_launch(void* const* d_in, const int* in_sizes, int n_in,
                              void* d_out, int out_size)
{
    const float* x   = (const float*)d_in[0];  // [256, 3072]
    const float* phi = (const float*)d_in[1];  // [3072, 4096]
    const float* smp = (const float*)d_in[2];  // scalar
    float* out = (float*)d_out;                // [256, 4096]

    __nv_bfloat16 *A1, *B1, *B2, *a0h, *rh;
    float *a0f;
    cudaGetSymbolAddress((void**)&A1, g_A1);
    cudaGetSymbolAddress((void**)&B1, g_B1);
    cudaGetSymbolAddress((void**)&B2, g_B2);
    cudaGetSymbolAddress((void**)&a0f, g_a0f);
    cudaGetSymbolAddress((void**)&a0h, g_a0h);
    cudaGetSymbolAddress((void**)&rh, g_rh);

    // conversions
    conv_x<<<(256 * 3072) / 256, 256>>>(x, A1);
    conv_phi<<<dim3(4096 / 32, 3072 / 64), 512>>>(phi, B1, B2);

    // GEMM1: a0 = A1 @ B1^T   M=256, N=4096, K=9216
    gemm_bf16<0><<<dim3(4096 / 64, 4), 256>>>(
        A1, B1, nullptr, nullptr, smp, a0f, a0h, 9216, 9216, 9216, 4096);

    // GEMM2: resid = a0h @ B2^T - x   M=256, N=3072, K=4096
    gemm_bf16<1><<<dim3(3072 / 64, 4), 256>>>(
        a0h, B2, x, nullptr, smp, nullptr, rh, 4096, 4096, 4096, 3072);

    // GEMM3: out = a0f - c19*(rh @ phT^T + sm*sign(a0f))   M=256, N=4096, K=3072
    gemm_bf16<2><<<dim3(4096 / 64, 4), 256>>>(
        rh, B1, nullptr, a0f, smp, out, nullptr, 3072, 3072, 9216, 4096);
}

// round 9
// speedup vs baseline: 3.6629x; 1.1645x over previous
#include <cuda_runtime.h>
#include <cuda_bf16.h>
#include <cstdint>

// Math (first-order collapse of 19 gradient steps, validated):
//   a0    = x @ phi
//   resid = a0 @ phi^T - x
//   out   = a0 - C19 * (resid @ phi + sm * sign(a0)),  C19 = 19*0.005/256
//
// All GEMMs: mma.sync.m16n8k16 bf16, fragments via ldmatrix.m8n8.x4.
// GEMM1 accuracy: bf16 hi/lo split via K-concat (K=9216):
//   A1 = [xh | xh | xl],  B1 = [phT | plT | phT]  ->  xh*ph + xh*pl + xl*ph
// GEMM2: B2 = bf16(phi) [3072 pix][4096 neu] (K=neuron contiguous).
// GEMM3: B = first 3072 K-cols of B1 (= phT).

#define DINL __device__ __forceinline__

// ---------------- scratch (device globals; no allocation allowed) -----------
__device__ __align__(1024) __nv_bfloat16 g_A1[256 * 9216];   // 4.7 MB
__device__ __align__(1024) __nv_bfloat16 g_B1[4096 * 9216];  // 75.5 MB
__device__ __align__(1024) __nv_bfloat16 g_B2[3072 * 4096];  // 25.2 MB
__device__ __align__(1024) float         g_a0f[256 * 4096];  // 4.2 MB
__device__ __align__(1024) __nv_bfloat16 g_a0h[256 * 4096];  // 2.1 MB
__device__ __align__(1024) __nv_bfloat16 g_rh[256 * 3072];   // 1.6 MB

// ---------------- PTX helpers -----------------------------------------------
DINL uint32_t smem_u32(const void* p) {
    uint32_t a;
    asm("{ .reg .u64 t; cvta.to.shared.u64 t, %1; cvt.u32.u64 %0, t; }"
        : "=r"(a) : "l"(p));
    return a;
}

#define CP16(dst, src) \
    asm volatile("cp.async.cg.shared.global [%0], [%1], 16;" :: "r"(dst), "l"(src) : "memory")
#define CP_COMMIT() asm volatile("cp.async.commit_group;" ::: "memory")
#define CP_WAIT1()  asm volatile("cp.async.wait_group 1;" ::: "memory")

#define LDSM4(r0, r1, r2, r3, addr) \
    asm volatile("ldmatrix.sync.aligned.m8n8.x4.shared.b16 {%0,%1,%2,%3}, [%4];" \
        : "=r"(r0), "=r"(r1), "=r"(r2), "=r"(r3) : "r"(addr))

DINL void mma16(float& d0, float& d1, float& d2, float& d3,
                uint32_t a0, uint32_t a1, uint32_t a2, uint32_t a3,
                uint32_t b0, uint32_t b1) {
    asm volatile(
        "mma.sync.aligned.m16n8k16.row.col.f32.bf16.bf16.f32 "
        "{%0,%1,%2,%3}, {%4,%5,%6,%7}, {%8,%9}, {%0,%1,%2,%3};"
        : "+f"(d0), "+f"(d1), "+f"(d2), "+f"(d3)
        : "r"(a0), "r"(a1), "r"(a2), "r"(a3), "r"(b0), "r"(b1));
}

DINL uint32_t pack2(float a, float b) {
    __nv_bfloat162 t = __floats2bfloat162_rn(a, b);
    return *reinterpret_cast<uint32_t*>(&t);
}

// ---------------- conversion kernels -----------------------------------------
__global__ __launch_bounds__(256) void conv_x(const float* __restrict__ x,
                                              __nv_bfloat16* __restrict__ A1) {
    int t = blockIdx.x * 256 + threadIdx.x;  // 256*3072 elements
    int m = t / 3072;
    int k = t - m * 3072;
    float f = x[t];
    __nv_bfloat16 h = __float2bfloat16(f);
    __nv_bfloat16 l = __float2bfloat16(f - __bfloat162float(h));
    size_t base = (size_t)m * 9216 + k;
    A1[base] = h;          // pairs with phT
    A1[base + 3072] = h;   // pairs with plT
    A1[base + 6144] = l;   // pairs with phT
}

// tile: 64 pixels (p) x 32 neurons (n), 512 threads
__global__ __launch_bounds__(512) void conv_phi(const float* __restrict__ phi,
                                                __nv_bfloat16* __restrict__ B1,
                                                __nv_bfloat16* __restrict__ B2) {
    __shared__ float tile[64][33];
    int p0 = blockIdx.y * 64, n0 = blockIdx.x * 32;
    int tx = threadIdx.x & 31, ty = threadIdx.x >> 5;  // ty 0..15
#pragma unroll
    for (int r = 0; r < 4; r++) {
        int pl = ty + 16 * r;
        float f = phi[(size_t)(p0 + pl) * 4096 + n0 + tx];
        tile[pl][tx] = f;
        B2[(size_t)(p0 + pl) * 4096 + n0 + tx] = __float2bfloat16(f);
    }
    __syncthreads();
    int pl2 = threadIdx.x & 63, nl2 = threadIdx.x >> 6;  // nl2 0..7
#pragma unroll
    for (int r = 0; r < 4; r++) {
        int nl = nl2 + 8 * r;
        float f = tile[pl2][nl];
        __nv_bfloat16 h = __float2bfloat16(f);
        __nv_bfloat16 l = __float2bfloat16(f - __bfloat162float(h));
        size_t base = (size_t)(n0 + nl) * 9216 + p0 + pl2;
        B1[base] = h;          // phT
        B1[base + 3072] = l;   // plT
        B1[base + 6144] = h;   // phT (pairs with xl)
    }
}

// ---------------- bf16 tensor-core GEMM --------------------------------------
// C[M,N] = sum_k A[m,k]*B[n,k].  BM=64, BN=64, BK=64 (bf16).
// 128 threads = 4 warps (2M x 2N); warp tile 32x32 = 2 m16 x 4 n8.
// 2-stage cp.async double buffer; static smem 36,864 B; ldmatrix fragments.
//
// MODE 0: a0f = acc (fp32), a0h = bf16(acc)
// MODE 1: Ch = bf16(acc - X)
// MODE 2: Cf = A0 - c19*(acc + sm*sign(A0))

constexpr int SAu = 36;             // u32 row stride (32 data + 4 pad)
constexpr int STG = 64 * SAu;       // 2304 u32 per tile per stage

template <int MODE>
__global__ __launch_bounds__(128) void gemm_bf16(
    const __nv_bfloat16* __restrict__ A, const __nv_bfloat16* __restrict__ B,
    const float* __restrict__ X, const float* __restrict__ A0,
    const float* __restrict__ SMP, float* __restrict__ Cf,
    __nv_bfloat16* __restrict__ Ch, int K, int lda, int ldb, int ldc)
{
    __shared__ uint32_t As[2 * STG];
    __shared__ uint32_t Bs[2 * STG];
    const uint32_t sA_u = smem_u32(As);
    const uint32_t sB_u = smem_u32(Bs);

    const int tid = threadIdx.x, lane = tid & 31, wid = tid >> 5;
    const int wm = wid >> 1, wn = wid & 1;     // 2 x 2 warps
    const int m0 = blockIdx.y * 64, n0 = blockIdx.x * 64;
    const int g = lane >> 2, c4 = lane & 3;

    // ldmatrix lane offsets
    const int j = lane >> 3, r8 = lane & 7;
    // A: j0=(m0-7,k0-7) j1=(m8-15,k0-7) j2=(m0-7,k8-15) j3=(m8-15,k8-15)
    const uint32_t aoff = (uint32_t)(((j & 1) * 8 + r8) * SAu + (j >> 1) * 4) * 4;
    // B: j0=(ks b0) j1=(ks b1) j2=(ks+1 b0) j3=(ks+1 b1)
    const uint32_t boff = (uint32_t)(r8 * SAu + (j & 1) * 4 + (j >> 1) * 8) * 4;

    float acc[2][4][4];
#pragma unroll
    for (int mt = 0; mt < 2; mt++)
#pragma unroll
        for (int nt = 0; nt < 4; nt++)
#pragma unroll
            for (int r = 0; r < 4; r++) acc[mt][nt][r] = 0.0f;

    const int nk = K >> 6;   // BK = 64 bf16

    auto load_tile = [&](int t, int slot) {
        // A: 64 rows x 128 B = 512 x 16B; 4 per thread
        const char* Ab = (const char*)(A + (size_t)m0 * lda + t * 64);
        uint32_t ad = sA_u + slot * STG * 4;
#pragma unroll
        for (int h = 0; h < 4; h++) {
            int idx = tid + h * 128;
            int row = idx >> 3, seg = idx & 7;
            CP16(ad + (uint32_t)(row * SAu + seg * 4) * 4,
                 Ab + (size_t)row * lda * 2 + seg * 16);
        }
        // B: 64 rows x 128 B; 4 per thread
        const char* Bb = (const char*)(B + (size_t)n0 * ldb + t * 64);
        uint32_t bd = sB_u + slot * STG * 4;
#pragma unroll
        for (int h = 0; h < 4; h++) {
            int idx = tid + h * 128;
            int row = idx >> 3, seg = idx & 7;
            CP16(bd + (uint32_t)(row * SAu + seg * 4) * 4,
                 Bb + (size_t)row * ldb * 2 + seg * 16);
        }
    };

    load_tile(0, 0);
    CP_COMMIT();

    for (int i = 0; i < nk; i++) {
        if (i + 1 < nk) {
            load_tile(i + 1, (i + 1) & 1);
            CP_COMMIT();
        }
        CP_WAIT1();
        __syncthreads();

        const uint32_t aBase = sA_u + ((i & 1) * STG + (wm * 32) * SAu) * 4 + aoff;
        const uint32_t bBase = sB_u + ((i & 1) * STG + (wn * 32) * SAu) * 4 + boff;

        // load all B fragments for this chunk: 4 nt x 2 ks-pairs = 8 LDSM.x4
        uint32_t bb[4][4][2];   // [nt][ks][2]
#pragma unroll
        for (int nt = 0; nt < 4; nt++)
#pragma unroll
            for (int p = 0; p < 2; p++) {
                uint32_t ba = bBase + (uint32_t)(nt * 8 * SAu + p * 16) * 4;
                LDSM4(bb[nt][2 * p][0], bb[nt][2 * p][1],
                      bb[nt][2 * p + 1][0], bb[nt][2 * p + 1][1], ba);
            }

#pragma unroll
        for (int ks = 0; ks < 4; ks++) {
            uint32_t aa[2][4];
#pragma unroll
            for (int mt = 0; mt < 2; mt++) {
                uint32_t aaddr = aBase + (uint32_t)(mt * 16 * SAu + ks * 8) * 4;
                LDSM4(aa[mt][0], aa[mt][1], aa[mt][2], aa[mt][3], aaddr);
            }
#pragma unroll
            for (int mt = 0; mt < 2; mt++)
#pragma unroll
                for (int nt = 0; nt < 4; nt++)
                    mma16(acc[mt][nt][0], acc[mt][nt][1], acc[mt][nt][2], acc[mt][nt][3],
                          aa[mt][0], aa[mt][1], aa[mt][2], aa[mt][3],
                          bb[nt][ks][0], bb[nt][ks][1]);
        }
        __syncthreads();
    }

    // ---- epilogue ----
    const float c19 = 19.0f * (0.005f / 256.0f);
    const float smv = (MODE == 2) ? SMP[0] : 0.0f;
#pragma unroll
    for (int mt = 0; mt < 2; mt++) {
        const int r0 = m0 + wm * 32 + mt * 16 + g;
#pragma unroll
        for (int nt = 0; nt < 4; nt++) {
            const int col = n0 + wn * 32 + nt * 8 + 2 * c4;
#pragma unroll
            for (int half = 0; half < 2; half++) {
                const int row = r0 + half * 8;
                const float d0 = acc[mt][nt][half * 2 + 0];
                const float d1 = acc[mt][nt][half * 2 + 1];
                const size_t idx = (size_t)row * ldc + col;
                if (MODE == 0) {
                    float2 v = {d0, d1};
                    *reinterpret_cast<float2*>(&Cf[idx]) = v;
                    *reinterpret_cast<uint32_t*>(&Ch[idx]) = pack2(d0, d1);
                } else if (MODE == 1) {
                    float2 xv = *reinterpret_cast<const float2*>(&X[idx]);
                    *reinterpret_cast<uint32_t*>(&Ch[idx]) = pack2(d0 - xv.x, d1 - xv.y);
                } else {
                    float2 av = *reinterpret_cast<const float2*>(&A0[idx]);
                    float s0 = (av.x > 0.f) ? 1.f : ((av.x < 0.f) ? -1.f : 0.f);
                    float s1 = (av.y > 0.f) ? 1.f : ((av.y < 0.f) ? -1.f : 0.f);
                    float2 v = {av.x - c19 * (d0 + smv * s0),
                                av.y - c19 * (d1 + smv * s1)};
                    *reinterpret_cast<float2*>(&Cf[idx]) = v;
                }
            }
        }
    }
}

// ---------------- launch -----------------------------------------------------
extern "C" void kernel_launch(void* const* d_in, const int* in_sizes, int n_in,
                              void* d_out, int out_size)
{
    const float* x   = (const float*)d_in[0];  // [256, 3072]
    const float* phi = (const float*)d_in[1];  // [3072, 4096]
    const float* smp = (const float*)d_in[2];  // scalar
    float* out = (float*)d_out;                // [256, 4096]

    __nv_bfloat16 *A1, *B1, *B2, *a0h, *rh;
    float *a0f;
    cudaGetSymbolAddress((void**)&A1, g_A1);
    cudaGetSymbolAddress((void**)&B1, g_B1);
    cudaGetSymbolAddress((void**)&B2, g_B2);
    cudaGetSymbolAddress((void**)&a0f, g_a0f);
    cudaGetSymbolAddress((void**)&a0h, g_a0h);
    cudaGetSymbolAddress((void**)&rh, g_rh);

    // conversions
    conv_x<<<(256 * 3072) / 256, 256>>>(x, A1);
    conv_phi<<<dim3(4096 / 32, 3072 / 64), 512>>>(phi, B1, B2);

    // GEMM1: a0 = A1 @ B1^T   M=256, N=4096, K=9216
    gemm_bf16<0><<<dim3(4096 / 64, 4), 128>>>(
        A1, B1, nullptr, nullptr, smp, a0f, a0h, 9216, 9216, 9216, 4096);

    // GEMM2: resid = a0h @ B2^T - x   M=256, N=3072, K=4096
    gemm_bf16<1><<<dim3(3072 / 64, 4), 128>>>(
        a0h, B2, x, nullptr, smp, nullptr, rh, 4096, 4096, 4096, 3072);

    // GEMM3: out = a0f - c19*(rh @ phT^T + sm*sign(a0f))   M=256, N=4096, K=3072
    gemm_bf16<2><<<dim3(4096 / 64, 4), 128>>>(
        rh, B1, nullptr, a0f, smp, out, nullptr, 3072, 3072, 9216, 4096);
}

// round 12
// speedup vs baseline: 3.7266x; 1.0174x over previous
#include <cuda_runtime.h>
#include <cuda_bf16.h>
#include <cstdint>

// Math (first-order collapse of 19 gradient steps, validated):
//   a0    = x @ phi
//   resid = a0 @ phi^T - x
//   out   = a0 - C19 * (resid @ phi + sm * sign(a0)),  C19 = 19*0.005/256
//
// All GEMMs: mma.sync.m16n8k16 bf16, ldmatrix fragments, warp-level split-K
// (8 warps = 2M x 2N x 2K).
// GEMM1 accuracy: bf16 hi/lo split via K-concat (K=9216):
//   A1 = [xh | xh | xl],  B1 = [phT | plT | phT]  ->  xh*ph + xh*pl + xl*ph
// GEMM2: B2 = bf16(phi) [3072 pix][4096 neu] (K=neuron contiguous).
// GEMM3: B = first 3072 K-cols of B1 (= phT).
//
// R12 FIX: final mainloop iteration uses cp.async.wait_group 0 (was 1) —
// closes (a) read race on the last K-tile and (b) write-after-write race
// between a still-in-flight cp.async group and the split-K reduction
// overlay on As. This was the source of the R11 post-timing divergence.

#define DINL __device__ __forceinline__

// ---------------- scratch (device globals; no allocation allowed) -----------
__device__ __align__(1024) __nv_bfloat16 g_A1[256 * 9216];   // 4.7 MB
__device__ __align__(1024) __nv_bfloat16 g_B1[4096 * 9216];  // 75.5 MB
__device__ __align__(1024) __nv_bfloat16 g_B2[3072 * 4096];  // 25.2 MB
__device__ __align__(1024) float         g_a0f[256 * 4096];  // 4.2 MB
__device__ __align__(1024) __nv_bfloat16 g_a0h[256 * 4096];  // 2.1 MB
__device__ __align__(1024) __nv_bfloat16 g_rh[256 * 3072];   // 1.6 MB

// ---------------- PTX helpers -----------------------------------------------
DINL uint32_t smem_u32(const void* p) {
    uint32_t a;
    asm("{ .reg .u64 t; cvta.to.shared.u64 t, %1; cvt.u32.u64 %0, t; }"
        : "=r"(a) : "l"(p));
    return a;
}

#define CP16(dst, src) \
    asm volatile("cp.async.cg.shared.global [%0], [%1], 16;" :: "r"(dst), "l"(src) : "memory")
#define CP_COMMIT() asm volatile("cp.async.commit_group;" ::: "memory")
#define CP_WAIT1()  asm volatile("cp.async.wait_group 1;" ::: "memory")
#define CP_WAIT0()  asm volatile("cp.async.wait_group 0;" ::: "memory")

#define LDSM4(r0, r1, r2, r3, addr) \
    asm volatile("ldmatrix.sync.aligned.m8n8.x4.shared.b16 {%0,%1,%2,%3}, [%4];" \
        : "=r"(r0), "=r"(r1), "=r"(r2), "=r"(r3) : "r"(addr))

DINL void mma16(float& d0, float& d1, float& d2, float& d3,
                uint32_t a0, uint32_t a1, uint32_t a2, uint32_t a3,
                uint32_t b0, uint32_t b1) {
    asm volatile(
        "mma.sync.aligned.m16n8k16.row.col.f32.bf16.bf16.f32 "
        "{%0,%1,%2,%3}, {%4,%5,%6,%7}, {%8,%9}, {%0,%1,%2,%3};"
        : "+f"(d0), "+f"(d1), "+f"(d2), "+f"(d3)
        : "r"(a0), "r"(a1), "r"(a2), "r"(a3), "r"(b0), "r"(b1));
}

DINL uint32_t pack2(float a, float b) {
    __nv_bfloat162 t = __floats2bfloat162_rn(a, b);
    return *reinterpret_cast<uint32_t*>(&t);
}

// ---------------- conversion kernels -----------------------------------------
__global__ __launch_bounds__(256) void conv_x(const float* __restrict__ x,
                                              __nv_bfloat16* __restrict__ A1) {
    int t = blockIdx.x * 256 + threadIdx.x;  // 256*3072 elements
    int m = t / 3072;
    int k = t - m * 3072;
    float f = x[t];
    __nv_bfloat16 h = __float2bfloat16(f);
    __nv_bfloat16 l = __float2bfloat16(f - __bfloat162float(h));
    size_t base = (size_t)m * 9216 + k;
    A1[base] = h;          // pairs with phT
    A1[base + 3072] = h;   // pairs with plT
    A1[base + 6144] = l;   // pairs with phT
}

// tile: 64 pixels (p) x 32 neurons (n), 512 threads
__global__ __launch_bounds__(512) void conv_phi(const float* __restrict__ phi,
                                                __nv_bfloat16* __restrict__ B1,
                                                __nv_bfloat16* __restrict__ B2) {
    __shared__ float tile[64][33];
    int p0 = blockIdx.y * 64, n0 = blockIdx.x * 32;
    int tx = threadIdx.x & 31, ty = threadIdx.x >> 5;  // ty 0..15
#pragma unroll
    for (int r = 0; r < 4; r++) {
        int pl = ty + 16 * r;
        float f = phi[(size_t)(p0 + pl) * 4096 + n0 + tx];
        tile[pl][tx] = f;
        B2[(size_t)(p0 + pl) * 4096 + n0 + tx] = __float2bfloat16(f);
    }
    __syncthreads();
    int pl2 = threadIdx.x & 63, nl2 = threadIdx.x >> 6;  // nl2 0..7
#pragma unroll
    for (int r = 0; r < 4; r++) {
        int nl = nl2 + 8 * r;
        float f = tile[pl2][nl];
        __nv_bfloat16 h = __float2bfloat16(f);
        __nv_bfloat16 l = __float2bfloat16(f - __bfloat162float(h));
        size_t base = (size_t)(n0 + nl) * 9216 + p0 + pl2;
        B1[base] = h;          // phT
        B1[base + 3072] = l;   // plT
        B1[base + 6144] = h;   // phT (pairs with xl)
    }
}

// ---------------- bf16 tensor-core GEMM --------------------------------------
// C[M,N] = sum_k A[m,k]*B[n,k].  BM=64, BN=64, BK=64 (bf16).
// 256 threads = 8 warps (2M x 2N x 2K split); warp tile 32x32, half K-chunk.
// 2-stage cp.async double buffer; static smem 36,864 B; ldmatrix fragments.
// End: wk=1 warps spill accs to smem (overlay on As), wk=0 reduce + epilogue.
//
// MODE 0: a0f = acc (fp32), a0h = bf16(acc)
// MODE 1: Ch = bf16(acc - X)
// MODE 2: Cf = A0 - c19*(acc + sm*sign(A0))

constexpr int SAu = 36;             // u32 row stride (32 data + 4 pad)
constexpr int STG = 64 * SAu;       // 2304 u32 per tile per stage

template <int MODE>
__global__ __launch_bounds__(256) void gemm_bf16(
    const __nv_bfloat16* __restrict__ A, const __nv_bfloat16* __restrict__ B,
    const float* __restrict__ X, const float* __restrict__ A0,
    const float* __restrict__ SMP, float* __restrict__ Cf,
    __nv_bfloat16* __restrict__ Ch, int K, int lda, int ldb, int ldc)
{
    __shared__ uint32_t As[2 * STG];
    __shared__ uint32_t Bs[2 * STG];
    const uint32_t sA_u = smem_u32(As);
    const uint32_t sB_u = smem_u32(Bs);

    const int tid = threadIdx.x, lane = tid & 31, wid = tid >> 5;
    const int wk = wid >> 2, wrem = wid & 3;
    const int wm = wrem >> 1, wn = wrem & 1;   // 2 x 2 spatial
    const int m0 = blockIdx.y * 64, n0 = blockIdx.x * 64;
    const int g = lane >> 2, c4 = lane & 3;

    // ldmatrix lane offsets
    const int j = lane >> 3, r8 = lane & 7;
    // A: j0=(m0-7,k0-7) j1=(m8-15,k0-7) j2=(m0-7,k8-15) j3=(m8-15,k8-15)
    const uint32_t aoff = (uint32_t)(((j & 1) * 8 + r8) * SAu + (j >> 1) * 4) * 4;
    // B: j0=(ks b0) j1=(ks b1) j2=(ks+1 b0) j3=(ks+1 b1)
    const uint32_t boff = (uint32_t)(r8 * SAu + (j & 1) * 4 + (j >> 1) * 8) * 4;

    float acc[2][4][4];
#pragma unroll
    for (int mt = 0; mt < 2; mt++)
#pragma unroll
        for (int nt = 0; nt < 4; nt++)
#pragma unroll
            for (int r = 0; r < 4; r++) acc[mt][nt][r] = 0.0f;

    const int nk = K >> 6;   // BK = 64 bf16

    auto load_tile = [&](int t, int slot) {
        // A: 64 rows x 128 B = 512 x 16B; 2 per thread
        const char* Ab = (const char*)(A + (size_t)m0 * lda + t * 64);
        uint32_t ad = sA_u + slot * STG * 4;
#pragma unroll
        for (int h = 0; h < 2; h++) {
            int idx = tid + h * 256;
            int row = idx >> 3, seg = idx & 7;
            CP16(ad + (uint32_t)(row * SAu + seg * 4) * 4,
                 Ab + (size_t)row * lda * 2 + seg * 16);
        }
        // B: 64 rows x 128 B; 2 per thread
        const char* Bb = (const char*)(B + (size_t)n0 * ldb + t * 64);
        uint32_t bd = sB_u + slot * STG * 4;
#pragma unroll
        for (int h = 0; h < 2; h++) {
            int idx = tid + h * 256;
            int row = idx >> 3, seg = idx & 7;
            CP16(bd + (uint32_t)(row * SAu + seg * 4) * 4,
                 Bb + (size_t)row * ldb * 2 + seg * 16);
        }
    };

    load_tile(0, 0);
    CP_COMMIT();

    for (int i = 0; i < nk; i++) {
        if (i + 1 < nk) {
            load_tile(i + 1, (i + 1) & 1);
            CP_COMMIT();
            CP_WAIT1();       // tile i resident; tile i+1 may be in flight
        } else {
            CP_WAIT0();       // FINAL tile: drain everything (race fix)
        }
        __syncthreads();

        const uint32_t aBase = sA_u + ((i & 1) * STG + (wm * 32) * SAu) * 4 + aoff;
        const uint32_t bBase = sB_u + ((i & 1) * STG + (wn * 32) * SAu) * 4 + boff;

        // B fragments for this warp's ks-pair (p = wk): 4 LDSM.x4
        uint32_t bb[4][2][2];   // [nt][q][2]  (q = ks within own pair)
#pragma unroll
        for (int nt = 0; nt < 4; nt++) {
            uint32_t ba = bBase + (uint32_t)(nt * 8 * SAu + wk * 16) * 4;
            LDSM4(bb[nt][0][0], bb[nt][0][1], bb[nt][1][0], bb[nt][1][1], ba);
        }

#pragma unroll
        for (int q = 0; q < 2; q++) {
            const int ks = wk * 2 + q;
            uint32_t aa[2][4];
#pragma unroll
            for (int mt = 0; mt < 2; mt++) {
                uint32_t aaddr = aBase + (uint32_t)(mt * 16 * SAu + ks * 8) * 4;
                LDSM4(aa[mt][0], aa[mt][1], aa[mt][2], aa[mt][3], aaddr);
            }
#pragma unroll
            for (int mt = 0; mt < 2; mt++)
#pragma unroll
                for (int nt = 0; nt < 4; nt++)
                    mma16(acc[mt][nt][0], acc[mt][nt][1], acc[mt][nt][2], acc[mt][nt][3],
                          aa[mt][0], aa[mt][1], aa[mt][2], aa[mt][3],
                          bb[nt][q][0], bb[nt][q][1]);
        }
        __syncthreads();
    }

    // ---- cross-warp K reduction (overlay on As: 4 pairs x 1056 floats) ----
    // Safe: CP_WAIT0 on the final iteration drained all cp.async groups.
    float* red = reinterpret_cast<float*>(As);
    const int pi = wm * 2 + wn;
    if (wk == 1) {
#pragma unroll
        for (int mt = 0; mt < 2; mt++)
#pragma unroll
            for (int nt = 0; nt < 4; nt++)
#pragma unroll
                for (int r = 0; r < 4; r++)
                    red[pi * 1056 + lane * 33 + mt * 16 + nt * 4 + r] = acc[mt][nt][r];
    }
    __syncthreads();
    if (wk == 1) return;

#pragma unroll
    for (int mt = 0; mt < 2; mt++)
#pragma unroll
        for (int nt = 0; nt < 4; nt++)
#pragma unroll
            for (int r = 0; r < 4; r++)
                acc[mt][nt][r] += red[pi * 1056 + lane * 33 + mt * 16 + nt * 4 + r];

    // ---- epilogue (wk == 0 warps only) ----
    const float c19 = 19.0f * (0.005f / 256.0f);
    const float smv = (MODE == 2) ? SMP[0] : 0.0f;
#pragma unroll
    for (int mt = 0; mt < 2; mt++) {
        const int r0 = m0 + wm * 32 + mt * 16 + g;
#pragma unroll
        for (int nt = 0; nt < 4; nt++) {
            const int col = n0 + wn * 32 + nt * 8 + 2 * c4;
#pragma unroll
            for (int half = 0; half < 2; half++) {
                const int row = r0 + half * 8;
                const float d0 = acc[mt][nt][half * 2 + 0];
                const float d1 = acc[mt][nt][half * 2 + 1];
                const size_t idx = (size_t)row * ldc + col;
                if (MODE == 0) {
                    float2 v = {d0, d1};
                    *reinterpret_cast<float2*>(&Cf[idx]) = v;
                    *reinterpret_cast<uint32_t*>(&Ch[idx]) = pack2(d0, d1);
                } else if (MODE == 1) {
                    float2 xv = *reinterpret_cast<const float2*>(&X[idx]);
                    *reinterpret_cast<uint32_t*>(&Ch[idx]) = pack2(d0 - xv.x, d1 - xv.y);
                } else {
                    float2 av = *reinterpret_cast<const float2*>(&A0[idx]);
                    float s0 = (av.x > 0.f) ? 1.f : ((av.x < 0.f) ? -1.f : 0.f);
                    float s1 = (av.y > 0.f) ? 1.f : ((av.y < 0.f) ? -1.f : 0.f);
                    float2 v = {av.x - c19 * (d0 + smv * s0),
                                av.y - c19 * (d1 + smv * s1)};
                    *reinterpret_cast<float2*>(&Cf[idx]) = v;
                }
            }
        }
    }
}

// ---------------- launch -----------------------------------------------------
extern "C" void kernel_launch(void* const* d_in, const int* in_sizes, int n_in,
                              void* d_out, int out_size)
{
    const float* x   = (const float*)d_in[0];  // [256, 3072]
    const float* phi = (const float*)d_in[1];  // [3072, 4096]
    const float* smp = (const float*)d_in[2];  // scalar
    float* out = (float*)d_out;                // [256, 4096]

    __nv_bfloat16 *A1, *B1, *B2, *a0h, *rh;
    float *a0f;
    cudaGetSymbolAddress((void**)&A1, g_A1);
    cudaGetSymbolAddress((void**)&B1, g_B1);
    cudaGetSymbolAddress((void**)&B2, g_B2);
    cudaGetSymbolAddress((void**)&a0f, g_a0f);
    cudaGetSymbolAddress((void**)&a0h, g_a0h);
    cudaGetSymbolAddress((void**)&rh, g_rh);

    // conversions
    conv_x<<<(256 * 3072) / 256, 256>>>(x, A1);
    conv_phi<<<dim3(4096 / 32, 3072 / 64), 512>>>(phi, B1, B2);

    // GEMM1: a0 = A1 @ B1^T   M=256, N=4096, K=9216
    gemm_bf16<0><<<dim3(4096 / 64, 4), 256>>>(
        A1, B1, nullptr, nullptr, smp, a0f, a0h, 9216, 9216, 9216, 4096);

    // GEMM2: resid = a0h @ B2^T - x   M=256, N=3072, K=4096
    gemm_bf16<1><<<dim3(3072 / 64, 4), 256>>>(
        a0h, B2, x, nullptr, smp, nullptr, rh, 4096, 4096, 4096, 3072);

    // GEMM3: out = a0f - c19*(rh @ phT^T + sm*sign(a0f))   M=256, N=4096, K=3072
    gemm_bf16<2><<<dim3(4096 / 64, 4), 256>>>(
        rh, B1, nullptr, a0f, smp, out, nullptr, 3072, 3072, 9216, 4096);
}

// round 13
// speedup vs baseline: 3.7684x; 1.0112x over previous
#include <cuda_runtime.h>
#include <cuda_bf16.h>
#include <cstdint>

// Math (first-order collapse of 19 gradient steps, validated):
//   a0    = x @ phi
//   resid = a0 @ phi^T - x
//   out   = a0 - C19 * (resid @ phi + sm * sign(a0)),  C19 = 19*0.005/256
//
// mma.sync.m16n8k16 bf16 + ldmatrix. R13: 4-stage BK=32 cp.async pipeline
// (prefetch distance 3, single __syncthreads per iteration) to cover the
// ~1300-cyc exposed load latency found in R12 (2-stage BK=64, distance 1).
// GEMM1 accuracy: bf16 hi/lo split via K-concat (K=9216):
//   A1 = [xh | xh | xl],  B1 = [phT | plT | phT]  ->  xh*ph + xh*pl + xl*ph

#define DINL __device__ __forceinline__

// ---------------- scratch (device globals; no allocation allowed) -----------
__device__ __align__(1024) __nv_bfloat16 g_A1[256 * 9216];   // 4.7 MB
__device__ __align__(1024) __nv_bfloat16 g_B1[4096 * 9216];  // 75.5 MB
__device__ __align__(1024) __nv_bfloat16 g_B2[3072 * 4096];  // 25.2 MB
__device__ __align__(1024) float         g_a0f[256 * 4096];  // 4.2 MB
__device__ __align__(1024) __nv_bfloat16 g_a0h[256 * 4096];  // 2.1 MB
__device__ __align__(1024) __nv_bfloat16 g_rh[256 * 3072];   // 1.6 MB

// ---------------- PTX helpers -----------------------------------------------
DINL uint32_t smem_u32(const void* p) {
    uint32_t a;
    asm("{ .reg .u64 t; cvta.to.shared.u64 t, %1; cvt.u32.u64 %0, t; }"
        : "=r"(a) : "l"(p));
    return a;
}

#define CP16(dst, src) \
    asm volatile("cp.async.cg.shared.global [%0], [%1], 16;" :: "r"(dst), "l"(src) : "memory")
#define CP_COMMIT() asm volatile("cp.async.commit_group;" ::: "memory")
#define CP_WAIT2()  asm volatile("cp.async.wait_group 2;" ::: "memory")

#define LDSM4(r0, r1, r2, r3, addr) \
    asm volatile("ldmatrix.sync.aligned.m8n8.x4.shared.b16 {%0,%1,%2,%3}, [%4];" \
        : "=r"(r0), "=r"(r1), "=r"(r2), "=r"(r3) : "r"(addr))

DINL void mma16(float& d0, float& d1, float& d2, float& d3,
                uint32_t a0, uint32_t a1, uint32_t a2, uint32_t a3,
                uint32_t b0, uint32_t b1) {
    asm volatile(
        "mma.sync.aligned.m16n8k16.row.col.f32.bf16.bf16.f32 "
        "{%0,%1,%2,%3}, {%4,%5,%6,%7}, {%8,%9}, {%0,%1,%2,%3};"
        : "+f"(d0), "+f"(d1), "+f"(d2), "+f"(d3)
        : "r"(a0), "r"(a1), "r"(a2), "r"(a3), "r"(b0), "r"(b1));
}

DINL uint32_t pack2(float a, float b) {
    __nv_bfloat162 t = __floats2bfloat162_rn(a, b);
    return *reinterpret_cast<uint32_t*>(&t);
}

// ---------------- conversion kernels -----------------------------------------
__global__ __launch_bounds__(256) void conv_x(const float* __restrict__ x,
                                              __nv_bfloat16* __restrict__ A1) {
    int t = blockIdx.x * 256 + threadIdx.x;  // 256*3072 elements
    int m = t / 3072;
    int k = t - m * 3072;
    float f = x[t];
    __nv_bfloat16 h = __float2bfloat16(f);
    __nv_bfloat16 l = __float2bfloat16(f - __bfloat162float(h));
    size_t base = (size_t)m * 9216 + k;
    A1[base] = h;          // pairs with phT
    A1[base + 3072] = h;   // pairs with plT
    A1[base + 6144] = l;   // pairs with phT
}

// tile: 64 pixels (p) x 32 neurons (n), 512 threads
__global__ __launch_bounds__(512) void conv_phi(const float* __restrict__ phi,
                                                __nv_bfloat16* __restrict__ B1,
                                                __nv_bfloat16* __restrict__ B2) {
    __shared__ float tile[64][33];
    int p0 = blockIdx.y * 64, n0 = blockIdx.x * 32;
    int tx = threadIdx.x & 31, ty = threadIdx.x >> 5;  // ty 0..15
#pragma unroll
    for (int r = 0; r < 4; r++) {
        int pl = ty + 16 * r;
        float f = phi[(size_t)(p0 + pl) * 4096 + n0 + tx];
        tile[pl][tx] = f;
        B2[(size_t)(p0 + pl) * 4096 + n0 + tx] = __float2bfloat16(f);
    }
    __syncthreads();
    int pl2 = threadIdx.x & 63, nl2 = threadIdx.x >> 6;  // nl2 0..7
#pragma unroll
    for (int r = 0; r < 4; r++) {
        int nl = nl2 + 8 * r;
        float f = tile[pl2][nl];
        __nv_bfloat16 h = __float2bfloat16(f);
        __nv_bfloat16 l = __float2bfloat16(f - __bfloat162float(h));
        size_t base = (size_t)(n0 + nl) * 9216 + p0 + pl2;
        B1[base] = h;          // phT
        B1[base + 3072] = l;   // plT
        B1[base + 6144] = h;   // phT (pairs with xl)
    }
}

// ---------------- bf16 tensor-core GEMM --------------------------------------
// C[M,N] = sum_k A[m,k]*B[n,k].  BM=64, BN=64, BK=32 (bf16).
// 128 threads = 4 warps (2M x 2N); warp tile 32x32 = 2 m16 x 4 n8 x 2 k16.
// 4-stage cp.async ring (prefetch distance 3), ONE __syncthreads per iter.
// Group discipline: commit EVERY iteration (possibly empty) so wait_group 2
// always drains exactly through tile i.  Static smem 40,960 B.
//
// MODE 0: a0f = acc (fp32), a0h = bf16(acc)
// MODE 1: Ch = bf16(acc - X)
// MODE 2: Cf = A0 - c19*(acc + sm*sign(A0))

constexpr int SAu = 20;             // u32 row stride (16 data + 4 pad); banks 20r%32 distinct over 8 rows
constexpr int STG = 64 * SAu;       // 1280 u32 per operand per stage

template <int MODE>
__global__ __launch_bounds__(128) void gemm_bf16(
    const __nv_bfloat16* __restrict__ A, const __nv_bfloat16* __restrict__ B,
    const float* __restrict__ X, const float* __restrict__ A0,
    const float* __restrict__ SMP, float* __restrict__ Cf,
    __nv_bfloat16* __restrict__ Ch, int K, int lda, int ldb, int ldc)
{
    __shared__ uint32_t As[4 * STG];
    __shared__ uint32_t Bs[4 * STG];
    const uint32_t sA_u = smem_u32(As);
    const uint32_t sB_u = smem_u32(Bs);

    const int tid = threadIdx.x, lane = tid & 31, wid = tid >> 5;
    const int wm = wid >> 1, wn = wid & 1;     // 2 x 2 warps
    const int m0 = blockIdx.y * 64, n0 = blockIdx.x * 64;
    const int g = lane >> 2, c4 = lane & 3;

    // ldmatrix lane offsets (bytes)
    const int j = lane >> 3, r8 = lane & 7;
    // A x4: j0=(m0-7,k0-7) j1=(m8-15,k0-7) j2=(m0-7,k8-15) j3=(m8-15,k8-15)
    const uint32_t aoffB = (uint32_t)(((j & 1) * 8 + r8) * SAu + (j >> 1) * 4) * 4;
    // B x4: j0=(ks0 b0) j1=(ks0 b1) j2=(ks1 b0) j3=(ks1 b1)
    const uint32_t boffB = (uint32_t)(r8 * SAu + (j & 1) * 4 + (j >> 1) * 8) * 4;

    float acc[2][4][4];
#pragma unroll
    for (int mt = 0; mt < 2; mt++)
#pragma unroll
        for (int nt = 0; nt < 4; nt++)
#pragma unroll
            for (int r = 0; r < 4; r++) acc[mt][nt][r] = 0.0f;

    const int nk = K >> 5;   // BK = 32 bf16

    auto load_tile = [&](int t, int slot) {
        // A: 64 rows x 64 B = 256 x 16B; 2 per thread
        const char* Ab = (const char*)A + ((size_t)m0 * lda + t * 32) * 2;
        uint32_t ad = sA_u + slot * STG * 4;
#pragma unroll
        for (int h = 0; h < 2; h++) {
            int idx = tid + h * 128;
            int row = idx >> 2, seg = idx & 3;
            CP16(ad + (uint32_t)(row * SAu + seg * 4) * 4,
                 Ab + (size_t)row * lda * 2 + seg * 16);
        }
        // B: 64 rows x 64 B; 2 per thread
        const char* Bb = (const char*)B + ((size_t)n0 * ldb + t * 32) * 2;
        uint32_t bd = sB_u + slot * STG * 4;
#pragma unroll
        for (int h = 0; h < 2; h++) {
            int idx = tid + h * 128;
            int row = idx >> 2, seg = idx & 3;
            CP16(bd + (uint32_t)(row * SAu + seg * 4) * 4,
                 Bb + (size_t)row * ldb * 2 + seg * 16);
        }
    };

    // prologue: tiles 0,1,2 in slots 0,1,2 (three groups)
    load_tile(0, 0); CP_COMMIT();
    load_tile(1, 1); CP_COMMIT();
    load_tile(2, 2); CP_COMMIT();

    for (int i = 0; i < nk; i++) {
        CP_WAIT2();            // group i drained -> tile i resident
        __syncthreads();       // all warps done reading slot (i-1)&3 (per-thread order)
        if (i + 3 < nk) load_tile(i + 3, (i + 3) & 3);
        CP_COMMIT();           // ALWAYS commit (possibly empty) -> group index == tile index

        const uint32_t aBase = sA_u + ((i & 3) * STG + (wm * 32) * SAu) * 4 + aoffB;
        const uint32_t bBase = sB_u + ((i & 3) * STG + (wn * 32) * SAu) * 4 + boffB;

        // B fragments: one x4 per nt covers both k16 steps
        uint32_t bb[4][2][2];   // [nt][ks][2]
#pragma unroll
        for (int nt = 0; nt < 4; nt++) {
            uint32_t ba = bBase + (uint32_t)(nt * 8 * SAu) * 4;
            LDSM4(bb[nt][0][0], bb[nt][0][1], bb[nt][1][0], bb[nt][1][1], ba);
        }

#pragma unroll
        for (int ks = 0; ks < 2; ks++) {
            uint32_t aa[2][4];
#pragma unroll
            for (int mt = 0; mt < 2; mt++) {
                uint32_t aaddr = aBase + (uint32_t)(mt * 16 * SAu + ks * 8) * 4;
                LDSM4(aa[mt][0], aa[mt][1], aa[mt][2], aa[mt][3], aaddr);
            }
#pragma unroll
            for (int mt = 0; mt < 2; mt++)
#pragma unroll
                for (int nt = 0; nt < 4; nt++)
                    mma16(acc[mt][nt][0], acc[mt][nt][1], acc[mt][nt][2], acc[mt][nt][3],
                          aa[mt][0], aa[mt][1], aa[mt][2], aa[mt][3],
                          bb[nt][ks][0], bb[nt][ks][1]);
        }
    }

    // ---- epilogue (registers -> global; no smem reuse, no extra sync) ----
    const float c19 = 19.0f * (0.005f / 256.0f);
    const float smv = (MODE == 2) ? SMP[0] : 0.0f;
#pragma unroll
    for (int mt = 0; mt < 2; mt++) {
        const int r0 = m0 + wm * 32 + mt * 16 + g;
#pragma unroll
        for (int nt = 0; nt < 4; nt++) {
            const int col = n0 + wn * 32 + nt * 8 + 2 * c4;
#pragma unroll
            for (int half = 0; half < 2; half++) {
                const int row = r0 + half * 8;
                const float d0 = acc[mt][nt][half * 2 + 0];
                const float d1 = acc[mt][nt][half * 2 + 1];
                const size_t idx = (size_t)row * ldc + col;
                if (MODE == 0) {
                    float2 v = {d0, d1};
                    *reinterpret_cast<float2*>(&Cf[idx]) = v;
                    *reinterpret_cast<uint32_t*>(&Ch[idx]) = pack2(d0, d1);
                } else if (MODE == 1) {
                    float2 xv = *reinterpret_cast<const float2*>(&X[idx]);
                    *reinterpret_cast<uint32_t*>(&Ch[idx]) = pack2(d0 - xv.x, d1 - xv.y);
                } else {
                    float2 av = *reinterpret_cast<const float2*>(&A0[idx]);
                    float s0 = (av.x > 0.f) ? 1.f : ((av.x < 0.f) ? -1.f : 0.f);
                    float s1 = (av.y > 0.f) ? 1.f : ((av.y < 0.f) ? -1.f : 0.f);
                    float2 v = {av.x - c19 * (d0 + smv * s0),
                                av.y - c19 * (d1 + smv * s1)};
                    *reinterpret_cast<float2*>(&Cf[idx]) = v;
                }
            }
        }
    }
}

// ---------------- launch -----------------------------------------------------
extern "C" void kernel_launch(void* const* d_in, const int* in_sizes, int n_in,
                              void* d_out, int out_size)
{
    const float* x   = (const float*)d_in[0];  // [256, 3072]
    const float* phi = (const float*)d_in[1];  // [3072, 4096]
    const float* smp = (const float*)d_in[2];  // scalar
    float* out = (float*)d_out;                // [256, 4096]

    __nv_bfloat16 *A1, *B1, *B2, *a0h, *rh;
    float *a0f;
    cudaGetSymbolAddress((void**)&A1, g_A1);
    cudaGetSymbolAddress((void**)&B1, g_B1);
    cudaGetSymbolAddress((void**)&B2, g_B2);
    cudaGetSymbolAddress((void**)&a0f, g_a0f);
    cudaGetSymbolAddress((void**)&a0h, g_a0h);
    cudaGetSymbolAddress((void**)&rh, g_rh);

    // conversions
    conv_x<<<(256 * 3072) / 256, 256>>>(x, A1);
    conv_phi<<<dim3(4096 / 32, 3072 / 64), 512>>>(phi, B1, B2);

    // GEMM1: a0 = A1 @ B1^T   M=256, N=4096, K=9216
    gemm_bf16<0><<<dim3(4096 / 64, 4), 128>>>(
        A1, B1, nullptr, nullptr, smp, a0f, a0h, 9216, 9216, 9216, 4096);

    // GEMM2: resid = a0h @ B2^T - x   M=256, N=3072, K=4096
    gemm_bf16<1><<<dim3(3072 / 64, 4), 128>>>(
        a0h, B2, x, nullptr, smp, nullptr, rh, 4096, 4096, 4096, 3072);

    // GEMM3: out = a0f - c19*(rh @ phT^T + sm*sign(a0f))   M=256, N=4096, K=3072
    gemm_bf16<2><<<dim3(4096 / 64, 4), 128>>>(
        rh, B1, nullptr, a0f, smp, out, nullptr, 3072, 3072, 9216, 4096);
}